// round 8
// baseline (speedup 1.0000x reference)
#include <cuda_runtime.h>

#define FULL 0xffffffffu
typedef unsigned long long u64;

// ---------- packed f32x2 helpers ----------
__device__ __forceinline__ u64 pk(float lo, float hi) {
    u64 r; asm("mov.b64 %0, {%1,%2};" : "=l"(r) : "f"(lo), "f"(hi)); return r;
}
__device__ __forceinline__ u64 pk2(float v) { return pk(v, v); }
__device__ __forceinline__ void upk(u64 a, float& lo, float& hi) {
    asm("mov.b64 {%0,%1}, %2;" : "=f"(lo), "=f"(hi) : "l"(a));
}
__device__ __forceinline__ u64 fma2(u64 a, u64 b, u64 c) {
    u64 d; asm("fma.rn.f32x2 %0, %1, %2, %3;" : "=l"(d) : "l"(a), "l"(b), "l"(c)); return d;
}
__device__ __forceinline__ u64 mul2(u64 a, u64 b) {
    u64 d; asm("mul.rn.f32x2 %0, %1, %2;" : "=l"(d) : "l"(a), "l"(b)); return d;
}
__device__ __forceinline__ u64 swp(u64 a) { float l, h; upk(a, l, h); return pk(h, l); }
__device__ __forceinline__ u64 shfx(u64 a, int m) {
    float l, h; upk(a, l, h);
    return pk(__shfl_xor_sync(FULL, l, m), __shfl_xor_sync(FULL, h, m));
}

// ---------- GF(2) frame tables (lane bits b4..b0 = wires 0..4) ----------
// F = per-layer lane CNOT chain (prefix-xor). Stored frame never permuted;
// gate at layer l, wire w pairs lanes across M = F^{-l}(e_w) with role
// predicate parity(lane & S), S = row_w(F^l).
__constant__ int cLM[6][5] = {
    {16, 8, 4, 2, 1},          // layer 0 (identity frame; unused by main loop)
    {24, 12, 6, 3, 1},
    {20, 10, 5, 2, 1},
    {30, 15, 7, 3, 1},
    {17, 8, 4, 2, 1},
    {25, 12, 6, 3, 1}};
__constant__ int cRS[6][5] = {
    {16, 8, 4, 2, 1},
    {16, 24, 28, 30, 31},
    {16, 8, 20, 10, 21},
    {16, 24, 12, 6, 19},
    {16, 8, 4, 2, 17},
    {16, 24, 28, 30, 15}};
// CNOT(4,5) control predicate for layer l's chain = row_w4(F^(l+1))
__constant__ int cC45[6] = {31, 21, 19, 17, 15, 5};
// final <Z_i> sign masks (rows of F^6), wires 0..4
#define Z0 16
#define Z1 8
#define Z2 20
#define Z3 10
#define Z4 5

// Per gate (layer*8+wire): 4 pre-packed u64 of fused C = Rz*Ry*Rx (SU(2) row 0):
// [0]=(C00r,C00i) [1]=(C01r,C01i) [2]=(C01i,-C01r) [3]=(C00i,-C00r)
__device__ u64 g_Gp[48 * 4];

__global__ void precompute_G(const float* __restrict__ w) {
    int tid = threadIdx.x;
    if (tid >= 48) return;
    float c0, s0, c1, s1, cz, sz;
    sincosf(0.5f * w[tid * 3 + 0], &s0, &c0);   // Rx
    sincosf(0.5f * w[tid * 3 + 1], &s1, &c1);   // Ry
    sincosf(0.5f * w[tid * 3 + 2], &sz, &cz);   // Rz
    float A00r = c1 * c0,  A00i = s1 * s0;
    float A01r = -s1 * c0, A01i = -c1 * s0;
    float C00r = cz * A00r + sz * A00i;
    float C00i = cz * A00i - sz * A00r;
    float C01r = cz * A01r + sz * A01i;
    float C01i = cz * A01i - sz * A01r;
    g_Gp[tid * 4 + 0] = pk(C00r, C00i);
    g_Gp[tid * 4 + 1] = pk(C01r, C01i);
    g_Gp[tid * 4 + 2] = pk(C01i, -C01r);
    g_Gp[tid * 4 + 3] = pk(C00i, -C00r);
}

// One warp per batch element. Amplitude n: lane bits 4..0 = n bits 7..3
// (wires 0..4), reg index t bits 2..0 = n bits 2..0 (wires 5,6,7).
// State packed SoA along t-bit0 (wire7): pr[j]=(re[2j],re[2j+1]), pi[j] same.
__global__ void __launch_bounds__(128, 10) qnn_kernel(const float* __restrict__ x,
                                                      float* __restrict__ out, int B) {
    __shared__ u64 sG[48 * 4];
    for (int k = threadIdx.x; k < 48 * 4; k += 128) sG[k] = g_Gp[k];
    __syncthreads();

    int warp = (blockIdx.x * blockDim.x + threadIdx.x) >> 5;
    int lane = threadIdx.x & 31;
    if (warp >= B) return;

    float se, ce, so, co;
    __sincosf(0.5f * x[2 * warp + 0], &se, &ce);  // RX enc (even wires)
    __sincosf(0.5f * x[2 * warp + 1], &so, &co);  // RY enc (odd wires)
    u64 ce2 = pk2(ce), se2 = pk2(se), co2 = pk2(co), so2 = pk2(so), nso2 = pk2(-so);

    // Fused gate matrix M = C*E(x): packed m00=(m00r,m00i), m01=(m01r,m01i).
#define GATE_M(g, wire, m00p, m01p)                                        \
    {                                                                      \
        ulonglong2 gxy = *reinterpret_cast<const ulonglong2*>(&sG[(g) * 4]); \
        if (((wire) & 1) == 0) {   /* RX */                                \
            ulonglong2 gzw = *reinterpret_cast<const ulonglong2*>(&sG[(g) * 4 + 2]); \
            m00p = fma2(ce2, gxy.x, mul2(se2, gzw.x));                     \
            m01p = fma2(ce2, gxy.y, mul2(se2, gzw.y));                     \
        } else {                   /* RY */                                \
            m00p = fma2(co2, gxy.x, mul2(so2, gxy.y));                     \
            m01p = fma2(co2, gxy.y, mul2(nso2, gxy.x));                    \
        }                                                                  \
    }

    u64 pr[4], pi[4];

    // ---------- layer 0: product state built directly from |0..0> ----------
    {
        float g0r[8], g0i[8], g1r[8], g1i[8];   // column 0: m00 and m10=-conj(m01)
#pragma unroll
        for (int wv = 0; wv < 8; wv++) {
            u64 m00p, m01p;
            GATE_M(wv, wv, m00p, m01p);
            float r0, i0, r1, i1;
            upk(m00p, r0, i0); upk(m01p, r1, i1);
            g0r[wv] = r0;  g0i[wv] = i0;
            g1r[wv] = -r1; g1i[wv] = i1;
        }
        float cr = 1.f, ci = 0.f;
#pragma unroll
        for (int wv = 0; wv < 5; wv++) {
            bool b = (lane >> (4 - wv)) & 1;
            float fr = b ? g1r[wv] : g0r[wv];
            float fi = b ? g1i[wv] : g0i[wv];
            float nr = cr * fr - ci * fi;
            float ni = cr * fi + ci * fr;
            cr = nr; ci = ni;
        }
        float ar[8], ai[8];
        {
            float d0r = cr * g0r[5] - ci * g0i[5], d0i = cr * g0i[5] + ci * g0r[5];
            float d1r = cr * g1r[5] - ci * g1i[5], d1i = cr * g1i[5] + ci * g1r[5];
            float e0r[4], e0i[4];
            e0r[0] = d0r * g0r[6] - d0i * g0i[6]; e0i[0] = d0r * g0i[6] + d0i * g0r[6];
            e0r[1] = d0r * g1r[6] - d0i * g1i[6]; e0i[1] = d0r * g1i[6] + d0i * g1r[6];
            e0r[2] = d1r * g0r[6] - d1i * g0i[6]; e0i[2] = d1r * g0i[6] + d1i * g0r[6];
            e0r[3] = d1r * g1r[6] - d1i * g1i[6]; e0i[3] = d1r * g1i[6] + d1i * g1r[6];
#pragma unroll
            for (int t = 0; t < 8; t++) {
                int e = t >> 1;
                bool b7 = t & 1;
                float fr = b7 ? g1r[7] : g0r[7];
                float fi = b7 ? g1i[7] : g0i[7];
                ar[t] = e0r[e] * fr - e0i[e] * fi;
                ai[t] = e0r[e] * fi + e0i[e] * fr;
            }
        }
#pragma unroll
        for (int j = 0; j < 4; j++) {
            pr[j] = pk(ar[2 * j], ar[2 * j + 1]);
            pi[j] = pk(ai[2 * j], ai[2 * j + 1]);
        }
    }

    // layer-0 CNOT chain (reg part only; lane part virtual) + layers 1..5
#pragma unroll
    for (int layer = 0; layer < 6; layer++) {
        if (layer > 0) {
#pragma unroll
            for (int wire = 0; wire < 8; wire++) {
                u64 m00p, m01p;
                GATE_M(layer * 8 + wire, wire, m00p, m01p);
                float m00r, m00i, m01r, m01i;
                upk(m00p, m00r, m00i); upk(m01p, m01r, m01i);

                if (wire < 5) {
                    // lane-level butterfly, frame-conjugated mask + role predicate
                    const int lm = cLM[layer][wire];
                    const int rs = cRS[layer][wire];
                    bool neg = (__popc(lane & rs) & 1) != 0;
                    float Piv = neg ? -m00i : m00i;
                    float Qrv = neg ? -m01r : m01r;
                    u64 Pr2 = pk2(m00r), Pi2 = pk2(Piv), nPi2 = pk2(-Piv);
                    u64 Qr2 = pk2(Qrv), Qi2 = pk2(m01i), nQi2 = pk2(-m01i);
#pragma unroll
                    for (int j = 0; j < 4; j++) {
                        u64 opr = shfx(pr[j], lm);
                        u64 opi = shfx(pi[j], lm);
                        u64 nr = fma2(Pr2, pr[j], fma2(nPi2, pi[j], fma2(Qr2, opr, mul2(nQi2, opi))));
                        u64 ni = fma2(Pi2, pr[j], fma2(Pr2, pi[j], fma2(Qi2, opr, mul2(Qr2, opi))));
                        pr[j] = nr; pi[j] = ni;
                    }
                } else if (wire < 7) {
                    // inter-register packed butterfly (wire5: stride 2; wire6: stride 1)
                    u64 r00 = pk2(m00r), i00 = pk2(m00i), ni00 = pk2(-m00i);
                    u64 r01 = pk2(m01r), nr01 = pk2(-m01r), i01 = pk2(m01i), ni01 = pk2(-m01i);
                    const int off = (wire == 5) ? 2 : 1;
#pragma unroll
                    for (int j = 0; j < 4; j++) {
                        if (j & off) continue;
                        int k = j | off;
                        u64 pA = pr[j], qA = pi[j], pB = pr[k], qB = pi[k];
                        pr[j] = fma2(r00, pA, fma2(ni00, qA, fma2(r01, pB, mul2(ni01, qB))));
                        pi[j] = fma2(i00, pA, fma2(r00, qA, fma2(i01, pB, mul2(r01, qB))));
                        pr[k] = fma2(nr01, pA, fma2(ni01, qA, fma2(r00, pB, mul2(i00, qB))));
                        pi[k] = fma2(i01, pA, fma2(nr01, qA, fma2(ni00, pB, mul2(r00, qB))));
                    }
                } else {
                    // wire7: intra-register butterfly with half-swaps
                    u64 A = pk2(m00r);
                    u64 Bc = pk(m01r, -m01r);
                    u64 Cc = pk(-m00i, m00i);
                    u64 D = pk2(-m01i);
                    u64 E = pk(m00i, -m00i);
                    u64 F = pk2(m01i);
#pragma unroll
                    for (int j = 0; j < 4; j++) {
                        u64 spr = swp(pr[j]), spi = swp(pi[j]);
                        u64 nr = fma2(A, pr[j], fma2(Bc, spr, fma2(Cc, pi[j], mul2(D, spi))));
                        u64 ni = fma2(E, pr[j], fma2(F, spr, fma2(A, pi[j], mul2(Bc, spi))));
                        pr[j] = nr; pi[j] = ni;
                    }
                }
            }
        }

        // ---- CNOT chain: lane part VIRTUAL (frame tracked), reg part physical ----
        // CNOT(4,5): control = logical wire4 after this layer's lane CNOTs
        //            = parity(lane & cC45[layer]); target reg bit2.
        {
            bool ctl = (__popc(lane & cC45[layer]) & 1) != 0;
#pragma unroll
            for (int k = 0; k < 2; k++) {
                u64 a = pr[k], b = pr[k + 2];
                pr[k] = ctl ? b : a; pr[k + 2] = ctl ? a : b;
                u64 c = pi[k], d = pi[k + 2];
                pi[k] = ctl ? d : c; pi[k + 2] = ctl ? c : d;
            }
        }
        // CNOT(5,6): swap reg pair 2<->3 (t: 4<->6, 5<->7)  [rename]
        {
            u64 t;
            t = pr[2]; pr[2] = pr[3]; pr[3] = t;
            t = pi[2]; pi[2] = pi[3]; pi[3] = t;
        }
        // CNOT(6,7): swap halves of regs 1 and 3 (t: 2<->3, 6<->7)
        pr[1] = swp(pr[1]); pr[3] = swp(pr[3]);
        pi[1] = swp(pi[1]); pi[3] = swp(pi[3]);
    }

    // ---------- expectation values ----------
    float p[8];
#pragma unroll
    for (int j = 0; j < 4; j++) {
        u64 pp = fma2(pr[j], pr[j], mul2(pi[j], pi[j]));
        upk(pp, p[2 * j], p[2 * j + 1]);
    }

    float tot = ((p[0] + p[1]) + (p[2] + p[3])) + ((p[4] + p[5]) + (p[6] + p[7]));
    float ev5 = (p[0] + p[1] + p[2] + p[3]) - (p[4] + p[5] + p[6] + p[7]);
    float ev6 = (p[0] + p[1] + p[4] + p[5]) - (p[2] + p[3] + p[6] + p[7]);
    float ev7 = (p[0] + p[2] + p[4] + p[6]) - (p[1] + p[3] + p[5] + p[7]);

    // Walsh-Hadamard butterfly on tot: after 5 steps lane k holds
    // X(k) = sum_s tot(s) * (-1)^{popc(s & k)}  -> ev_i = X(Z_i).
    // Plain sum butterflies for ev5..7 (all lanes end with the warp sum).
#pragma unroll
    for (int b = 0; b < 5; b++) {
        const int m = 1 << b;
        float o = __shfl_xor_sync(FULL, tot, m);
        tot = (lane & m) ? (o - tot) : (o + tot);
        ev5 += __shfl_xor_sync(FULL, ev5, m);
        ev6 += __shfl_xor_sync(FULL, ev6, m);
        ev7 += __shfl_xor_sync(FULL, ev7, m);
    }

    const float PI = 3.14159265358979f;
    float* o = out + warp * 8;
    if (lane == Z0) o[0] = tot * PI;
    if (lane == Z1) o[1] = tot * PI;
    if (lane == Z2) o[2] = tot * PI;
    if (lane == Z3) o[3] = tot * PI;
    if (lane == Z4) o[4] = tot * PI;
    if (lane == 0) {
        o[5] = ev5 * PI;
        o[6] = ev6 * PI;
        o[7] = ev7 * PI;
    }
#undef GATE_M
}

extern "C" void kernel_launch(void* const* d_in, const int* in_sizes, int n_in,
                              void* d_out, int out_size) {
    const float* x = (const float*)d_in[0];   // [B, 2]
    const float* w = (const float*)d_in[1];   // [6, 8, 3]
    float* out = (float*)d_out;               // [B, 8]
    int B = in_sizes[0] / 2;

    precompute_G<<<1, 64>>>(w);
    int threads = 128;
    int blocks = (B * 32 + threads - 1) / threads;
    qnn_kernel<<<blocks, threads>>>(x, out, B);
}

// round 9
// speedup vs baseline: 1.0624x; 1.0624x over previous
#include <cuda_runtime.h>

#define FULL 0xffffffffu
typedef unsigned long long u64;

// ---------- packed f32x2 helpers ----------
__device__ __forceinline__ u64 pk(float lo, float hi) {
    u64 r; asm("mov.b64 %0, {%1,%2};" : "=l"(r) : "f"(lo), "f"(hi)); return r;
}
__device__ __forceinline__ u64 pk2(float v) { return pk(v, v); }
__device__ __forceinline__ void upk(u64 a, float& lo, float& hi) {
    asm("mov.b64 {%0,%1}, %2;" : "=f"(lo), "=f"(hi) : "l"(a));
}
__device__ __forceinline__ u64 fma2(u64 a, u64 b, u64 c) {
    u64 d; asm("fma.rn.f32x2 %0, %1, %2, %3;" : "=l"(d) : "l"(a), "l"(b), "l"(c)); return d;
}
__device__ __forceinline__ u64 mul2(u64 a, u64 b) {
    u64 d; asm("mul.rn.f32x2 %0, %1, %2;" : "=l"(d) : "l"(a), "l"(b)); return d;
}
__device__ __forceinline__ u64 swp(u64 a) { float l, h; upk(a, l, h); return pk(h, l); }
__device__ __forceinline__ u64 shfx(u64 a, int m) {
    float l, h; upk(a, l, h);
    return pk(__shfl_xor_sync(FULL, l, m), __shfl_xor_sync(FULL, h, m));
}
__device__ __forceinline__ u64 shfi(u64 a, int s) {
    float l, h; upk(a, l, h);
    return pk(__shfl_sync(FULL, l, s), __shfl_sync(FULL, h, s));
}

// Per gate (layer*8+wire): 4 pre-packed u64 of fused C = Rz*Ry*Rx (SU(2) row 0):
// [0]=(C00r,C00i) [1]=(C01r,C01i) [2]=(C01i,-C01r) [3]=(C00i,-C00r)
__device__ u64 g_Gp[48 * 4];

__global__ void precompute_G(const float* __restrict__ w) {
    int tid = threadIdx.x;
    if (tid >= 48) return;
    float c0, s0, c1, s1, cz, sz;
    sincosf(0.5f * w[tid * 3 + 0], &s0, &c0);   // Rx
    sincosf(0.5f * w[tid * 3 + 1], &s1, &c1);   // Ry
    sincosf(0.5f * w[tid * 3 + 2], &sz, &cz);   // Rz
    float A00r = c1 * c0,  A00i = s1 * s0;
    float A01r = -s1 * c0, A01i = -c1 * s0;
    float C00r = cz * A00r + sz * A00i;
    float C00i = cz * A00i - sz * A00r;
    float C01r = cz * A01r + sz * A01i;
    float C01i = cz * A01i - sz * A01r;
    g_Gp[tid * 4 + 0] = pk(C00r, C00i);
    g_Gp[tid * 4 + 1] = pk(C01r, C01i);
    g_Gp[tid * 4 + 2] = pk(C01i, -C01r);
    g_Gp[tid * 4 + 3] = pk(C00i, -C00r);
}

// One warp per batch element. Amplitude n: lane bits 4..0 = n bits 7..3
// (wires 0..4), reg index t bits 2..0 = n bits 2..0 (wires 5,6,7).
// State packed SoA along t-bit0 (wire7): pr[j]=(re[2j],re[2j+1]), pi[j] same.
__global__ void __launch_bounds__(128, 10) qnn_kernel(const float* __restrict__ x,
                                                      float* __restrict__ out, int B) {
    __shared__ u64 sG[48 * 4];
    for (int k = threadIdx.x; k < 48 * 4; k += 128) sG[k] = g_Gp[k];
    __syncthreads();

    int warp = (blockIdx.x * blockDim.x + threadIdx.x) >> 5;
    int lane = threadIdx.x & 31;
    if (warp >= B) return;

    float se, ce, so, co;
    __sincosf(0.5f * x[2 * warp + 0], &se, &ce);  // RX enc (even wires)
    __sincosf(0.5f * x[2 * warp + 1], &so, &co);  // RY enc (odd wires)
    u64 ce2 = pk2(ce), se2 = pk2(se), co2 = pk2(co), so2 = pk2(so), nso2 = pk2(-so);

    // Fused gate matrix M = C*E(x): packed m00=(m00r,m00i), m01=(m01r,m01i).
#define GATE_M(g, wire, m00p, m01p)                                        \
    {                                                                      \
        ulonglong2 gxy = *reinterpret_cast<const ulonglong2*>(&sG[(g) * 4]); \
        if (((wire) & 1) == 0) {   /* RX */                                \
            ulonglong2 gzw = *reinterpret_cast<const ulonglong2*>(&sG[(g) * 4 + 2]); \
            m00p = fma2(ce2, gxy.x, mul2(se2, gzw.x));                     \
            m01p = fma2(ce2, gxy.y, mul2(se2, gzw.y));                     \
        } else {                   /* RY */                                \
            m00p = fma2(co2, gxy.x, mul2(so2, gxy.y));                     \
            m01p = fma2(co2, gxy.y, mul2(nso2, gxy.x));                    \
        }                                                                  \
    }

    u64 pr[4], pi[4];

    // ---------- layer 0: product state built directly from |0..0> ----------
    {
        float g0r[8], g0i[8], g1r[8], g1i[8];   // column 0: m00 and m10=-conj(m01)
#pragma unroll
        for (int wv = 0; wv < 8; wv++) {
            u64 m00p, m01p;
            GATE_M(wv, wv, m00p, m01p);
            float r0, i0, r1, i1;
            upk(m00p, r0, i0); upk(m01p, r1, i1);
            g0r[wv] = r0;  g0i[wv] = i0;
            g1r[wv] = -r1; g1i[wv] = i1;
        }
        float cr = 1.f, ci = 0.f;
#pragma unroll
        for (int wv = 0; wv < 5; wv++) {
            bool b = (lane >> (4 - wv)) & 1;
            float fr = b ? g1r[wv] : g0r[wv];
            float fi = b ? g1i[wv] : g0i[wv];
            float nr = cr * fr - ci * fi;
            float ni = cr * fi + ci * fr;
            cr = nr; ci = ni;
        }
        float ar[8], ai[8];
        {
            float d0r = cr * g0r[5] - ci * g0i[5], d0i = cr * g0i[5] + ci * g0r[5];
            float d1r = cr * g1r[5] - ci * g1i[5], d1i = cr * g1i[5] + ci * g1r[5];
            float e0r[4], e0i[4];
            e0r[0] = d0r * g0r[6] - d0i * g0i[6]; e0i[0] = d0r * g0i[6] + d0i * g0r[6];
            e0r[1] = d0r * g1r[6] - d0i * g1i[6]; e0i[1] = d0r * g1i[6] + d0i * g1r[6];
            e0r[2] = d1r * g0r[6] - d1i * g0i[6]; e0i[2] = d1r * g0i[6] + d1i * g0r[6];
            e0r[3] = d1r * g1r[6] - d1i * g1i[6]; e0i[3] = d1r * g1i[6] + d1i * g1r[6];
#pragma unroll
            for (int t = 0; t < 8; t++) {
                int e = t >> 1;
                bool b7 = t & 1;
                float fr = b7 ? g1r[7] : g0r[7];
                float fi = b7 ? g1i[7] : g0i[7];
                ar[t] = e0r[e] * fr - e0i[e] * fi;
                ai[t] = e0r[e] * fi + e0i[e] * fr;
            }
        }
#pragma unroll
        for (int j = 0; j < 4; j++) {
            pr[j] = pk(ar[2 * j], ar[2 * j + 1]);
            pi[j] = pk(ai[2 * j], ai[2 * j + 1]);
        }
    }

    // lane permutation source for the composed CNOT(0,1)..CNOT(3,4) chain
    int src = lane;
    src ^= (src >> 1) & 1;
    src ^= (src >> 1) & 2;
    src ^= (src >> 1) & 4;
    src ^= (src >> 1) & 8;
    const bool ctl45 = (lane & 1) != 0;

    // layer-0 CNOT chain + layers 1..5 (gates + CNOTs)
#pragma unroll
    for (int layer = 0; layer < 6; layer++) {
        if (layer > 0) {
#pragma unroll
            for (int wire = 0; wire < 8; wire++) {
                u64 m00p, m01p;
                GATE_M(layer * 8 + wire, wire, m00p, m01p);
                float m00r, m00i, m01r, m01i;
                upk(m00p, m00r, m00i); upk(m01p, m01r, m01i);

                if (wire < 5) {
                    // lane-level butterfly via shfl.xor
                    const int lm = 1 << (4 - wire);
                    bool neg = (lane & lm) != 0;
                    float Piv = neg ? -m00i : m00i;
                    float Qrv = neg ? -m01r : m01r;
                    u64 Pr2 = pk2(m00r), Pi2 = pk2(Piv), nPi2 = pk2(-Piv);
                    u64 Qr2 = pk2(Qrv), Qi2 = pk2(m01i), nQi2 = pk2(-m01i);
#pragma unroll
                    for (int j = 0; j < 4; j++) {
                        u64 opr = shfx(pr[j], lm);
                        u64 opi = shfx(pi[j], lm);
                        u64 nr = fma2(Pr2, pr[j], fma2(nPi2, pi[j], fma2(Qr2, opr, mul2(nQi2, opi))));
                        u64 ni = fma2(Pi2, pr[j], fma2(Pr2, pi[j], fma2(Qi2, opr, mul2(Qr2, opi))));
                        pr[j] = nr; pi[j] = ni;
                    }
                } else if (wire < 7) {
                    // inter-register packed butterfly (wire5: stride 2; wire6: stride 1)
                    u64 r00 = pk2(m00r), i00 = pk2(m00i), ni00 = pk2(-m00i);
                    u64 r01 = pk2(m01r), nr01 = pk2(-m01r), i01 = pk2(m01i), ni01 = pk2(-m01i);
                    const int off = (wire == 5) ? 2 : 1;
#pragma unroll
                    for (int j = 0; j < 4; j++) {
                        if (j & off) continue;
                        int k = j | off;
                        u64 pA = pr[j], qA = pi[j], pB = pr[k], qB = pi[k];
                        pr[j] = fma2(r00, pA, fma2(ni00, qA, fma2(r01, pB, mul2(ni01, qB))));
                        pi[j] = fma2(i00, pA, fma2(r00, qA, fma2(i01, pB, mul2(r01, qB))));
                        pr[k] = fma2(nr01, pA, fma2(ni01, qA, fma2(r00, pB, mul2(i00, qB))));
                        pi[k] = fma2(i01, pA, fma2(nr01, qA, fma2(ni00, pB, mul2(r00, qB))));
                    }
                } else {
                    // wire7: intra-register butterfly with half-swaps
                    u64 A = pk2(m00r);
                    u64 Bc = pk(m01r, -m01r);
                    u64 Cc = pk(-m00i, m00i);
                    u64 D = pk2(-m01i);
                    u64 E = pk(m00i, -m00i);
                    u64 F = pk2(m01i);
#pragma unroll
                    for (int j = 0; j < 4; j++) {
                        u64 spr = swp(pr[j]), spi = swp(pi[j]);
                        u64 nr = fma2(A, pr[j], fma2(Bc, spr, fma2(Cc, pi[j], mul2(D, spi))));
                        u64 ni = fma2(E, pr[j], fma2(F, spr, fma2(A, pi[j], mul2(Bc, spi))));
                        pr[j] = nr; pi[j] = ni;
                    }
                }
            }
        }

        // ---- CNOT chain ----
        // CNOT(0,1)..CNOT(3,4): composed lane permutation
#pragma unroll
        for (int j = 0; j < 4; j++) {
            pr[j] = shfi(pr[j], src);
            pi[j] = shfi(pi[j], src);
        }
        // CNOT(4,5): control lane bit0, target reg bit2
#pragma unroll
        for (int k = 0; k < 2; k++) {
            u64 a = pr[k], b = pr[k + 2];
            pr[k] = ctl45 ? b : a; pr[k + 2] = ctl45 ? a : b;
            u64 c = pi[k], d = pi[k + 2];
            pi[k] = ctl45 ? d : c; pi[k + 2] = ctl45 ? c : d;
        }
        // CNOT(5,6): swap reg pair 2<->3 (t: 4<->6, 5<->7)  [rename]
        {
            u64 t;
            t = pr[2]; pr[2] = pr[3]; pr[3] = t;
            t = pi[2]; pi[2] = pi[3]; pi[3] = t;
        }
        // CNOT(6,7): swap halves of regs 1 and 3 (t: 2<->3, 6<->7)
        pr[1] = swp(pr[1]); pr[3] = swp(pr[3]);
        pi[1] = swp(pi[1]); pi[3] = swp(pi[3]);
    }

    // ---------- expectation values ----------
    float p[8];
#pragma unroll
    for (int j = 0; j < 4; j++) {
        u64 pp = fma2(pr[j], pr[j], mul2(pi[j], pi[j]));
        upk(pp, p[2 * j], p[2 * j + 1]);
    }

    float tot = ((p[0] + p[1]) + (p[2] + p[3])) + ((p[4] + p[5]) + (p[6] + p[7]));
    float ev5 = (p[0] + p[1] + p[2] + p[3]) - (p[4] + p[5] + p[6] + p[7]);
    float ev6 = (p[0] + p[1] + p[4] + p[5]) - (p[2] + p[3] + p[6] + p[7]);
    float ev7 = (p[0] + p[2] + p[4] + p[6]) - (p[1] + p[3] + p[5] + p[7]);

    // Walsh-Hadamard butterfly on tot: after 5 steps lane k holds
    // X(k) = sum_s tot(s) * (-1)^{popc(s & k)}.
    // Physical frame: Z_i (wires 0..4) = lane bit (4-i) -> ev_i = X(1<<(4-i)).
    // Plain sum butterflies for ev5..7 (every lane ends with the warp sum).
#pragma unroll
    for (int b = 0; b < 5; b++) {
        const int m = 1 << b;
        float o = __shfl_xor_sync(FULL, tot, m);
        tot = (lane & m) ? (o - tot) : (o + tot);
        ev5 += __shfl_xor_sync(FULL, ev5, m);
        ev6 += __shfl_xor_sync(FULL, ev6, m);
        ev7 += __shfl_xor_sync(FULL, ev7, m);
    }

    const float PI = 3.14159265358979f;
    float* o = out + warp * 8;
    if (lane == 16) o[0] = tot * PI;
    if (lane == 8)  o[1] = tot * PI;
    if (lane == 4)  o[2] = tot * PI;
    if (lane == 2)  o[3] = tot * PI;
    if (lane == 1)  o[4] = tot * PI;
    if (lane == 0) {
        o[5] = ev5 * PI;
        o[6] = ev6 * PI;
        o[7] = ev7 * PI;
    }
#undef GATE_M
}

extern "C" void kernel_launch(void* const* d_in, const int* in_sizes, int n_in,
                              void* d_out, int out_size) {
    const float* x = (const float*)d_in[0];   // [B, 2]
    const float* w = (const float*)d_in[1];   // [6, 8, 3]
    float* out = (float*)d_out;               // [B, 8]
    int B = in_sizes[0] / 2;

    precompute_G<<<1, 64>>>(w);
    int threads = 128;
    int blocks = (B * 32 + threads - 1) / threads;
    qnn_kernel<<<blocks, threads>>>(x, out, B);
}